// round 1
// baseline (speedup 1.0000x reference)
#include <cuda_runtime.h>
#include <math.h>

// Shapes (fixed per reference):
//   segin:   [2, 4, 96, 160, 160] f32
//   edgein:  [2, 1, 96, 160, 160] f32
//   segmask: [2, 1, 96, 160, 160] i32 (values 0..3)
//   edgemask:[2, 1, 96, 160, 160] i32 (values 0..1)
// Output: float[2] = (region_loss, edge_loss)

#define NCLASS 4
#define SPATIAL 2457600            // 96*160*160
#define NBATCH 2
#define SV (SPATIAL / 4)           // 614400 float4s per (n, channel)
#define TOTV (NBATCH * SV)         // 1228800 vec4 voxel-groups

// Global accumulators (double):
// [0..3]  intersect[c]   = sum probs[c] where target==c
// [4..7]  sumprob[c]     = sum probs[c]
// [8..11] cnt[c]         = count(target==c)
// [12]    bce_pos        = sum bce where edgemask==1
// [13]    bce_neg        = sum bce where edgemask==0
// [14]    pos_num
// [15]    neg_num
__device__ double g_acc[16];

__global__ void zero_acc_kernel() {
    if (threadIdx.x < 16) g_acc[threadIdx.x] = 0.0;
}

__inline__ __device__ float warp_red_f(float v) {
    #pragma unroll
    for (int o = 16; o > 0; o >>= 1) v += __shfl_down_sync(0xffffffffu, v, o);
    return v;
}
__inline__ __device__ int warp_red_i(int v) {
    #pragma unroll
    for (int o = 16; o > 0; o >>= 1) v += __shfl_down_sync(0xffffffffu, v, o);
    return v;
}

struct Acc {
    float inter[NCLASS];
    float sp[NCLASS];
    int   cnt[NCLASS];
    float bceP, bceN;
    int   posN, negN;
};

__inline__ __device__ void process_voxel(
    float x0, float x1, float x2, float x3, int t,
    float ex, int et, Acc& a)
{
    // softmax over 4 channels
    float m  = fmaxf(fmaxf(x0, x1), fmaxf(x2, x3));
    float e0 = __expf(x0 - m);
    float e1 = __expf(x1 - m);
    float e2 = __expf(x2 - m);
    float e3 = __expf(x3 - m);
    float inv = 1.0f / (e0 + e1 + e2 + e3);
    float p0 = e0 * inv, p1 = e1 * inv, p2 = e2 * inv, p3 = e3 * inv;
    a.sp[0] += p0; a.sp[1] += p1; a.sp[2] += p2; a.sp[3] += p3;

    bool t0 = (t == 0), t1 = (t == 1), t2 = (t == 2), t3 = (t == 3);
    a.inter[0] += t0 ? p0 : 0.0f;  a.cnt[0] += (int)t0;
    a.inter[1] += t1 ? p1 : 0.0f;  a.cnt[1] += (int)t1;
    a.inter[2] += t2 ? p2 : 0.0f;  a.cnt[2] += (int)t2;
    a.inter[3] += t3 ? p3 : 0.0f;  a.cnt[3] += (int)t3;

    // numerically stable BCE-with-logits
    float tf  = (float)et;
    float bce = fmaxf(ex, 0.0f) - ex * tf + log1pf(__expf(-fabsf(ex)));
    bool pos = (et == 1);
    a.bceP += pos ? bce : 0.0f;
    a.bceN += pos ? 0.0f : bce;
    a.posN += (int)pos;
    a.negN += (int)(!pos);
}

__global__ void __launch_bounds__(256)
fused_loss_kernel(const float4* __restrict__ seg,
                  const float4* __restrict__ edge,
                  const int4*   __restrict__ smask,
                  const int4*   __restrict__ emask)
{
    Acc a;
    #pragma unroll
    for (int c = 0; c < NCLASS; c++) { a.inter[c] = 0.f; a.sp[c] = 0.f; a.cnt[c] = 0; }
    a.bceP = 0.f; a.bceN = 0.f; a.posN = 0; a.negN = 0;

    const int stride = gridDim.x * blockDim.x;
    for (int v = blockIdx.x * blockDim.x + threadIdx.x; v < TOTV; v += stride) {
        int nb   = v / SV;                     // batch index
        int base = v + nb * (NCLASS - 1) * SV; // channel-0 vec index in segin

        float4 c0 = seg[base];
        float4 c1 = seg[base + SV];
        float4 c2 = seg[base + 2 * SV];
        float4 c3 = seg[base + 3 * SV];
        int4   tt = smask[v];
        float4 ee = edge[v];
        int4   et = emask[v];

        process_voxel(c0.x, c1.x, c2.x, c3.x, tt.x, ee.x, et.x, a);
        process_voxel(c0.y, c1.y, c2.y, c3.y, tt.y, ee.y, et.y, a);
        process_voxel(c0.z, c1.z, c2.z, c3.z, tt.z, ee.z, et.z, a);
        process_voxel(c0.w, c1.w, c2.w, c3.w, tt.w, ee.w, et.w, a);
    }

    // --- block reduction ---
    __shared__ float sf[10];   // inter[4], sp[4], bceP, bceN
    __shared__ int   si[6];    // cnt[4], posN, negN
    if (threadIdx.x < 10) sf[threadIdx.x] = 0.0f;
    if (threadIdx.x < 6)  si[threadIdx.x] = 0;
    __syncthreads();

    #pragma unroll
    for (int c = 0; c < NCLASS; c++) {
        a.inter[c] = warp_red_f(a.inter[c]);
        a.sp[c]    = warp_red_f(a.sp[c]);
        a.cnt[c]   = warp_red_i(a.cnt[c]);
    }
    a.bceP = warp_red_f(a.bceP);
    a.bceN = warp_red_f(a.bceN);
    a.posN = warp_red_i(a.posN);
    a.negN = warp_red_i(a.negN);

    if ((threadIdx.x & 31) == 0) {
        #pragma unroll
        for (int c = 0; c < NCLASS; c++) {
            atomicAdd(&sf[c],     a.inter[c]);
            atomicAdd(&sf[4 + c], a.sp[c]);
            atomicAdd(&si[c],     a.cnt[c]);
        }
        atomicAdd(&sf[8], a.bceP);
        atomicAdd(&sf[9], a.bceN);
        atomicAdd(&si[4], a.posN);
        atomicAdd(&si[5], a.negN);
    }
    __syncthreads();

    if (threadIdx.x == 0) {
        #pragma unroll
        for (int c = 0; c < NCLASS; c++) {
            atomicAdd(&g_acc[c],     (double)sf[c]);
            atomicAdd(&g_acc[4 + c], (double)sf[4 + c]);
            atomicAdd(&g_acc[8 + c], (double)si[c]);
        }
        atomicAdd(&g_acc[12], (double)sf[8]);
        atomicAdd(&g_acc[13], (double)sf[9]);
        atomicAdd(&g_acc[14], (double)si[4]);
        atomicAdd(&g_acc[15], (double)si[5]);
    }
}

__global__ void finalize_kernel(float* __restrict__ out) {
    if (threadIdx.x == 0 && blockIdx.x == 0) {
        const double smooth = 1e-5;
        double dice_sum = 0.0;
        #pragma unroll
        for (int c = 0; c < NCLASS; c++) {
            double I = g_acc[c];
            double P = g_acc[4 + c];
            double T = g_acc[8 + c];
            dice_sum += (2.0 * I + smooth) / (P + T + smooth);
        }
        out[0] = (float)(1.0 - dice_sum / (double)NCLASS);

        double posn = g_acc[14];
        double negn = g_acc[15];
        double tot  = posn + negn;
        double edge_loss = (negn / tot * g_acc[12] + posn / tot * g_acc[13]) / tot;
        out[1] = (float)edge_loss;
    }
}

extern "C" void kernel_launch(void* const* d_in, const int* in_sizes, int n_in,
                              void* d_out, int out_size) {
    const float4* seg   = (const float4*)d_in[0];
    const float4* edge  = (const float4*)d_in[1];
    const int4*   smask = (const int4*)d_in[2];
    const int4*   emask = (const int4*)d_in[3];
    float* out = (float*)d_out;

    zero_acc_kernel<<<1, 32>>>();
    // 1184 blocks (8 per SM on 148 SMs) x 256 threads; each thread ~4 vec4 iters
    fused_loss_kernel<<<1184, 256>>>(seg, edge, smask, emask);
    finalize_kernel<<<1, 32>>>(out);
}

// round 2
// speedup vs baseline: 1.1815x; 1.1815x over previous
#include <cuda_runtime.h>
#include <math.h>

// Shapes (fixed):
//   segin:   [2, 4, 96, 160, 160] f32
//   edgein:  [2, 1, 96, 160, 160] f32
//   segmask: [2, 1, 96, 160, 160] i32 (0..3)
//   edgemask:[2, 1, 96, 160, 160] i32 (0..1)
// Output: float[2] = (region_loss, edge_loss)

#define NCLASS  4
#define SPATIAL 2457600               // 96*160*160
#define NBATCH  2
#define SV      (SPATIAL / 4)         // 614400 float4s per (n, channel)
#define TOTV    (NBATCH * SV)         // 1228800 vec4 voxel-groups
#define NBLK    592                   // 148 SMs x 4 blocks
#define NTHR    256

// Per-block partials. Components:
// [0..3] intersect[c], [4..7] sumprob[c], [8..11] cnt[c],
// [12] bceP, [13] bceN, [14] posN, [15] negN
__device__ float g_part[NBLK][16];
__device__ int   g_done = 0;

__inline__ __device__ float wredf(float v) {
    #pragma unroll
    for (int o = 16; o > 0; o >>= 1) v += __shfl_down_sync(0xffffffffu, v, o);
    return v;
}
__inline__ __device__ int wredi(int v) {
    #pragma unroll
    for (int o = 16; o > 0; o >>= 1) v += __shfl_down_sync(0xffffffffu, v, o);
    return v;
}

__global__ void __launch_bounds__(NTHR, 4)
fused_loss_kernel(const float4* __restrict__ seg,
                  const float4* __restrict__ edge,
                  const int4*   __restrict__ smask,
                  const int4*   __restrict__ emask,
                  float* __restrict__ out)
{
    float in0 = 0.f, in1 = 0.f, in2 = 0.f, in3 = 0.f;   // intersect per class
    float sp0 = 0.f, sp1 = 0.f, sp2 = 0.f, sp3 = 0.f;   // sum prob per class
    float bp  = 0.f, bn  = 0.f;                          // bce pos/neg buckets
    int   pk  = 0;                                       // byte-packed class counts
    int   pos = 0;                                       // edge positives

    const int stride = NBLK * NTHR;
    for (int v = blockIdx.x * NTHR + threadIdx.x; v < TOTV; v += stride) {
        int base = (v >= SV) ? v + 3 * SV : v;   // channel-0 vec idx in segin

        float4 c0 = __ldcs(seg + base);
        float4 c1 = __ldcs(seg + base + SV);
        float4 c2 = __ldcs(seg + base + 2 * SV);
        float4 c3 = __ldcs(seg + base + 3 * SV);
        int4   tt = __ldcs(smask + v);
        float4 ee = __ldcs(edge + v);
        int4   et = __ldcs(emask + v);

        #define VOX(x0, x1, x2, x3, t, ex, eti) do {                         \
            float m  = fmaxf(fmaxf(x0, x1), fmaxf(x2, x3));                  \
            float e0 = __expf((x0) - m);                                     \
            float e1 = __expf((x1) - m);                                     \
            float e2 = __expf((x2) - m);                                     \
            float e3 = __expf((x3) - m);                                     \
            float inv = __fdividef(1.0f, e0 + e1 + e2 + e3);                 \
            float p0 = e0 * inv, p1 = e1 * inv, p2 = e2 * inv, p3 = e3 * inv;\
            sp0 += p0; sp1 += p1; sp2 += p2; sp3 += p3;                      \
            in0 += ((t) == 0) ? p0 : 0.f;                                    \
            in1 += ((t) == 1) ? p1 : 0.f;                                    \
            in2 += ((t) == 2) ? p2 : 0.f;                                    \
            in3 += ((t) == 3) ? p3 : 0.f;                                    \
            pk  += 1 << ((t) * 8);                                           \
            float ax = fabsf(ex);                                            \
            float b  = fmaxf((ex), 0.f) - (ex) * (float)(eti)                \
                       + __logf(1.0f + __expf(-ax));                         \
            bp += (eti) ? b : 0.f;                                           \
            bn += (eti) ? 0.f : b;                                           \
            pos += (eti);                                                    \
        } while (0)

        VOX(c0.x, c1.x, c2.x, c3.x, tt.x, ee.x, et.x);
        VOX(c0.y, c1.y, c2.y, c3.y, tt.y, ee.y, et.y);
        VOX(c0.z, c1.z, c2.z, c3.z, tt.z, ee.z, et.z);
        VOX(c0.w, c1.w, c2.w, c3.w, tt.w, ee.w, et.w);
        #undef VOX
    }

    // ---- block reduction ----
    in0 = wredf(in0); in1 = wredf(in1); in2 = wredf(in2); in3 = wredf(in3);
    sp0 = wredf(sp0); sp1 = wredf(sp1); sp2 = wredf(sp2); sp3 = wredf(sp3);
    bp  = wredf(bp);  bn  = wredf(bn);
    int c0i =  pk        & 255;
    int c1i = (pk >> 8)  & 255;
    int c2i = (pk >> 16) & 255;
    int c3i = (pk >> 24) & 255;
    c0i = wredi(c0i); c1i = wredi(c1i); c2i = wredi(c2i); c3i = wredi(c3i);
    pos = wredi(pos);

    __shared__ float sf[16];
    if (threadIdx.x < 16) sf[threadIdx.x] = 0.f;
    __syncthreads();
    if ((threadIdx.x & 31) == 0) {
        atomicAdd(&sf[0],  in0); atomicAdd(&sf[1],  in1);
        atomicAdd(&sf[2],  in2); atomicAdd(&sf[3],  in3);
        atomicAdd(&sf[4],  sp0); atomicAdd(&sf[5],  sp1);
        atomicAdd(&sf[6],  sp2); atomicAdd(&sf[7],  sp3);
        atomicAdd(&sf[8],  (float)c0i); atomicAdd(&sf[9],  (float)c1i);
        atomicAdd(&sf[10], (float)c2i); atomicAdd(&sf[11], (float)c3i);
        atomicAdd(&sf[12], bp); atomicAdd(&sf[13], bn);
        atomicAdd(&sf[14], (float)pos);
        atomicAdd(&sf[15], (float)(c0i + c1i + c2i + c3i - pos)); // negN
    }
    __syncthreads();
    if (threadIdx.x < 16) g_part[blockIdx.x][threadIdx.x] = sf[threadIdx.x];
    __threadfence();

    __shared__ int sdone;
    if (threadIdx.x == 0) sdone = atomicAdd(&g_done, 1);
    __syncthreads();

    if (sdone == NBLK - 1) {
        __threadfence();  // acquire all blocks' partials
        // 256 threads: component c = tid&15, row group r0 = tid>>4
        int c  = threadIdx.x & 15;
        int r0 = threadIdx.x >> 4;
        double s = 0.0;
        for (int r = r0; r < NBLK; r += 16) s += (double)g_part[r][c];
        __shared__ double red[NTHR];
        red[threadIdx.x] = s;
        __syncthreads();
        if (threadIdx.x < 16) {
            double tot = 0.0;
            #pragma unroll
            for (int k = 0; k < 16; k++) tot += red[c + 16 * k];
            red[threadIdx.x] = tot;
        }
        __syncthreads();
        if (threadIdx.x == 0) {
            const double smooth = 1e-5;
            double dsum = 0.0;
            #pragma unroll
            for (int cc = 0; cc < NCLASS; cc++) {
                double I = red[cc], P = red[4 + cc], T = red[8 + cc];
                dsum += (2.0 * I + smooth) / (P + T + smooth);
            }
            out[0] = (float)(1.0 - dsum / (double)NCLASS);

            double pn = red[14], nn = red[15], tt = pn + nn;
            out[1] = (float)((nn * red[12] + pn * red[13]) / (tt * tt));

            g_done = 0;   // reset for next (graph-replayed) launch
        }
    }
}

extern "C" void kernel_launch(void* const* d_in, const int* in_sizes, int n_in,
                              void* d_out, int out_size) {
    const float4* seg   = (const float4*)d_in[0];
    const float4* edge  = (const float4*)d_in[1];
    const int4*   smask = (const int4*)d_in[2];
    const int4*   emask = (const int4*)d_in[3];
    float* out = (float*)d_out;

    fused_loss_kernel<<<NBLK, NTHR>>>(seg, edge, smask, emask, out);
}